// round 4
// baseline (speedup 1.0000x reference)
#include <cuda_runtime.h>
#include <cstdint>

#define MAXN 100000
#define MAXE 3200000

typedef unsigned long long ull;

// ---------------- scratch (device globals) ----------------------------------
__device__ float g_deg [MAXN];
__device__ float g_dinv[MAXN];
__device__ float g_t1  [MAXN * 64];   // x@W1
__device__ float g_s   [MAXN * 64];   // node state
__device__ float g_u   [MAXN * 64];   // gathered state (GGC)
__device__ float g_t2  [MAXN * 16];   // s@W2
// CSR
__device__ int   g_off [MAXN + 1];
__device__ int   g_cur [MAXN];
__device__ ull   g_egcn[MAXE];        // packed (src, w*dinv[src])
__device__ ull   g_eggc[MAXE];        // packed (src, w)
__device__ float g_wc  [2 * 64 * 192]; // Wg@Wih^T per layer  [k][f]
__device__ float g_whht[64 * 192];     // Whh^T               [k][f]

__device__ __forceinline__ float sigmoidf_(float x) { return 1.0f / (1.0f + expf(-x)); }

__device__ __forceinline__ ull packsw(int s, float w) {
    return ((ull)__float_as_uint(w) << 32) | (unsigned)s;
}
__device__ __forceinline__ int  pk_src(ull m) { return (int)(unsigned)m; }
__device__ __forceinline__ float pk_w(ull m)  { return __uint_as_float((unsigned)(m >> 32)); }

// ---- packed f32x2 helpers ---------------------------------------------------
__device__ __forceinline__ ull dup2(float a) {
    ull r; asm("mov.b64 %0,{%1,%1};" : "=l"(r) : "f"(a)); return r;
}
__device__ __forceinline__ void fma2(ull& d, ull a, ull b) {
    asm("fma.rn.f32x2 %0,%1,%2,%0;" : "+l"(d) : "l"(a), "l"(b));
}
__device__ __forceinline__ float2 unpk(ull v) {
    float2 f; asm("mov.b64 {%0,%1},%2;" : "=f"(f.x), "=f"(f.y) : "l"(v)); return f;
}

// ---------------- CSR build --------------------------------------------------
__global__ void init_kernel(float* deg, int* cnt, int n) {
    int i = blockIdx.x * blockDim.x + threadIdx.x;
    if (i < n) { deg[i] = 1.0f; cnt[i] = 0; }
}

__global__ void count_kernel(const int* __restrict__ col, const float* __restrict__ w,
                             int* cnt, float* deg, int e) {
    int i = blockIdx.x * blockDim.x + threadIdx.x;
    if (i < e) {
        int c = col[i];
        atomicAdd(cnt + c, 1);
        atomicAdd(deg + c, w[i]);
    }
}

// exclusive scan of cnt -> off/cur, plus dinv = deg^-1/2
__global__ void scan_dinv_kernel(const int* __restrict__ cnt, int* __restrict__ off,
                                 int* __restrict__ cur,
                                 const float* __restrict__ deg, float* __restrict__ dinv,
                                 int n) {
    __shared__ int part[1024];
    int t = threadIdx.x;
    int chunk = (n + 1023) >> 10;
    int lo = t * chunk;
    int hi = min(lo + chunk, n);
    int s = 0;
    for (int i = lo; i < hi; i++) s += cnt[i];
    part[t] = s;
    __syncthreads();
    for (int d = 1; d < 1024; d <<= 1) {
        int add = (t >= d) ? part[t - d] : 0;
        __syncthreads();
        part[t] += add;
        __syncthreads();
    }
    int base = part[t] - s;   // exclusive
    for (int i = lo; i < hi; i++) {
        int c = cnt[i];       // read BEFORE cur[i] store (cnt aliases cur)
        off[i] = base; cur[i] = base;
        base += c;
        float d = deg[i];
        dinv[i] = (d > 0.0f) ? rsqrtf(d) : 0.0f;
    }
    if (t == 0) off[n] = part[1023];
}

__global__ void fill_kernel(const int* __restrict__ row, const int* __restrict__ col,
                            const float* __restrict__ w, const float* __restrict__ dinv,
                            int* cur, ull* __restrict__ egcn, ull* __restrict__ eggc, int e) {
    int i = blockIdx.x * blockDim.x + threadIdx.x;
    if (i >= e) return;
    int r = row[i];
    float ww = w[i];
    int pos = atomicAdd(cur + col[i], 1);
    eggc[pos] = packsw(r, ww);
    egcn[pos] = packsw(r, ww * __ldg(dinv + r));
}

// Wc[k,f] = sum_j Wg[layer][k][j] * Wih[f][j]   (Wc : [64,192])
__global__ void wc_kernel(const float* __restrict__ Wg, const float* __restrict__ Wih,
                          float* __restrict__ Wc) {
    int idx = blockIdx.x * blockDim.x + threadIdx.x;
    if (idx >= 64 * 192) return;
    int k = idx / 192, f = idx % 192;
    float s = 0.0f;
#pragma unroll 8
    for (int j = 0; j < 64; j++) s = fmaf(Wg[k * 64 + j], Wih[f * 64 + j], s);
    Wc[idx] = s;
}

__global__ void whht_kernel(const float* __restrict__ Whh, float* __restrict__ WhhT) {
    int idx = blockIdx.x * blockDim.x + threadIdx.x;
    if (idx >= 64 * 192) return;
    int k = idx / 192, f = idx % 192;
    WhhT[idx] = Whh[f * 64 + k];
}

// ---------------- CSR gather (F=64), fused epilogues -------------------------
// EPI 0: plain weighted sum -> dst            (GGC message aggregation)
// EPI 1: GCN1: relu(dinv*acc + dinv^2*self + bias) -> dst
template<int EPI>
__global__ __launch_bounds__(256)
void gather64_kernel(const float* __restrict__ feat, const float* __restrict__ selff,
                     float* __restrict__ dst,
                     const int* __restrict__ off, const ull* __restrict__ meta,
                     const float* __restrict__ dinv, const float* __restrict__ bias, int n) {
    int node = (blockIdx.x * blockDim.x + threadIdx.x) >> 5;
    if (node >= n) return;
    int lane = threadIdx.x & 31;
    int h = lane >> 4;        // 0/1 edge parity
    int l = lane & 15;        // float4 lane in 64-dim row

    int beg = __ldg(off + node);
    int end = __ldg(off + node + 1);

    const float* fbase = feat + l * 4;

    float4 a0 = make_float4(0.f, 0.f, 0.f, 0.f);
    float4 a1 = make_float4(0.f, 0.f, 0.f, 0.f);
    float4 a2 = make_float4(0.f, 0.f, 0.f, 0.f);
    float4 a3 = make_float4(0.f, 0.f, 0.f, 0.f);

    int j = beg + h;
    for (; j + 6 < end; j += 8) {
        ull m0 = __ldg(meta + j);
        ull m1 = __ldg(meta + j + 2);
        ull m2 = __ldg(meta + j + 4);
        ull m3 = __ldg(meta + j + 6);
        float4 v0 = *reinterpret_cast<const float4*>(fbase + (size_t)pk_src(m0) * 64);
        float4 v1 = *reinterpret_cast<const float4*>(fbase + (size_t)pk_src(m1) * 64);
        float4 v2 = *reinterpret_cast<const float4*>(fbase + (size_t)pk_src(m2) * 64);
        float4 v3 = *reinterpret_cast<const float4*>(fbase + (size_t)pk_src(m3) * 64);
        float w0 = pk_w(m0), w1 = pk_w(m1), w2 = pk_w(m2), w3 = pk_w(m3);
        a0.x = fmaf(w0, v0.x, a0.x); a0.y = fmaf(w0, v0.y, a0.y);
        a0.z = fmaf(w0, v0.z, a0.z); a0.w = fmaf(w0, v0.w, a0.w);
        a1.x = fmaf(w1, v1.x, a1.x); a1.y = fmaf(w1, v1.y, a1.y);
        a1.z = fmaf(w1, v1.z, a1.z); a1.w = fmaf(w1, v1.w, a1.w);
        a2.x = fmaf(w2, v2.x, a2.x); a2.y = fmaf(w2, v2.y, a2.y);
        a2.z = fmaf(w2, v2.z, a2.z); a2.w = fmaf(w2, v2.w, a2.w);
        a3.x = fmaf(w3, v3.x, a3.x); a3.y = fmaf(w3, v3.y, a3.y);
        a3.z = fmaf(w3, v3.z, a3.z); a3.w = fmaf(w3, v3.w, a3.w);
    }
    for (; j < end; j += 2) {
        ull m0 = __ldg(meta + j);
        float4 v0 = *reinterpret_cast<const float4*>(fbase + (size_t)pk_src(m0) * 64);
        float w0 = pk_w(m0);
        a0.x = fmaf(w0, v0.x, a0.x); a0.y = fmaf(w0, v0.y, a0.y);
        a0.z = fmaf(w0, v0.z, a0.z); a0.w = fmaf(w0, v0.w, a0.w);
    }
    a0.x += a1.x + a2.x + a3.x;
    a0.y += a1.y + a2.y + a3.y;
    a0.z += a1.z + a2.z + a3.z;
    a0.w += a1.w + a2.w + a3.w;

    a0.x += __shfl_down_sync(0xffffffffu, a0.x, 16);
    a0.y += __shfl_down_sync(0xffffffffu, a0.y, 16);
    a0.z += __shfl_down_sync(0xffffffffu, a0.z, 16);
    a0.w += __shfl_down_sync(0xffffffffu, a0.w, 16);

    if (h == 0) {
        float4 o;
        if (EPI == 1) {
            float di = __ldg(dinv + node);
            float4 sv = *reinterpret_cast<const float4*>(selff + (size_t)node * 64 + l * 4);
            float4 bv = *reinterpret_cast<const float4*>(bias + l * 4);
            o.x = fmaxf(fmaf(di, a0.x, fmaf(di * di, sv.x, bv.x)), 0.0f);
            o.y = fmaxf(fmaf(di, a0.y, fmaf(di * di, sv.y, bv.y)), 0.0f);
            o.z = fmaxf(fmaf(di, a0.z, fmaf(di * di, sv.z, bv.z)), 0.0f);
            o.w = fmaxf(fmaf(di, a0.w, fmaf(di * di, sv.w, bv.w)), 0.0f);
        } else {
            o = a0;
        }
        *reinterpret_cast<float4*>(dst + (size_t)node * 64 + l * 4) = o;
    }
}

// ---------------- CSR gather (F=16) + GCN epilogue + log_softmax --------------
__global__ __launch_bounds__(256)
void gather16_lsm_kernel(const float* __restrict__ feat, float* __restrict__ out,
                         const int* __restrict__ off, const ull* __restrict__ meta,
                         const float* __restrict__ dinv, const float* __restrict__ b2, int n) {
    int node = (blockIdx.x * blockDim.x + threadIdx.x) >> 5;
    if (node >= n) return;
    int lane = threadIdx.x & 31;
    int h = lane >> 2;        // 0..7 edge slot
    int l = lane & 3;

    int beg = __ldg(off + node);
    int end = __ldg(off + node + 1);

    float4 a = make_float4(0.f, 0.f, 0.f, 0.f);
    for (int j = beg + h; j < end; j += 8) {
        ull m = __ldg(meta + j);
        float w0 = pk_w(m);
        float4 v = *reinterpret_cast<const float4*>(feat + (size_t)pk_src(m) * 16 + l * 4);
        a.x = fmaf(w0, v.x, a.x); a.y = fmaf(w0, v.y, a.y);
        a.z = fmaf(w0, v.z, a.z); a.w = fmaf(w0, v.w, a.w);
    }
#pragma unroll
    for (int o = 16; o >= 4; o >>= 1) {
        a.x += __shfl_down_sync(0xffffffffu, a.x, o);
        a.y += __shfl_down_sync(0xffffffffu, a.y, o);
        a.z += __shfl_down_sync(0xffffffffu, a.z, o);
        a.w += __shfl_down_sync(0xffffffffu, a.w, o);
    }

    if (h == 0) {
        float di = __ldg(dinv + node);
        float4 sv = *reinterpret_cast<const float4*>(feat + (size_t)node * 16 + l * 4);
        float4 bv = *reinterpret_cast<const float4*>(b2 + l * 4);
        float4 v;
        v.x = fmaf(di, a.x, fmaf(di * di, sv.x, bv.x));
        v.y = fmaf(di, a.y, fmaf(di * di, sv.y, bv.y));
        v.z = fmaf(di, a.z, fmaf(di * di, sv.z, bv.z));
        v.w = fmaf(di, a.w, fmaf(di * di, sv.w, bv.w));
        float mx = fmaxf(fmaxf(v.x, v.y), fmaxf(v.z, v.w));
        mx = fmaxf(mx, __shfl_xor_sync(0x0000000Fu, mx, 1));
        mx = fmaxf(mx, __shfl_xor_sync(0x0000000Fu, mx, 2));
        float se = expf(v.x - mx) + expf(v.y - mx) + expf(v.z - mx) + expf(v.w - mx);
        se += __shfl_xor_sync(0x0000000Fu, se, 1);
        se += __shfl_xor_sync(0x0000000Fu, se, 2);
        float lse = mx + logf(se);
        float4 o;
        o.x = v.x - lse; o.y = v.y - lse; o.z = v.z - lse; o.w = v.w - lse;
        *reinterpret_cast<float4*>(out + (size_t)node * 16 + l * 4) = o;
    }
}

// ---------------- register-tiled fp32 GEMM with packed FFMA2 ------------------
template<int BM, int BN, int BK, int TM, int TN>
__global__ __launch_bounds__((BM/TM)*(BN/TN))
void gemm_kernel(const float* __restrict__ A, const float* __restrict__ B,
                 float* __restrict__ C, int M, int K, int Nb) {
    constexpr int NT  = (BM / TM) * (BN / TN);
    constexpr int BMP = BM + 4;
    constexpr int BNP = BN + 4;
    __shared__ __align__(16) float As[BK][BMP];
    __shared__ __align__(16) float Bs[BK][BNP];

    const int tid = threadIdx.x;
    const int tr  = tid / (BN / TN);
    const int tc  = tid % (BN / TN);
    const int cm  = blockIdx.x * BM;
    const int cn  = blockIdx.y * BN;

    ull acc2[TM][TN / 2];
#pragma unroll
    for (int i = 0; i < TM; i++)
#pragma unroll
        for (int j = 0; j < TN / 2; j++) acc2[i][j] = 0ULL;

    for (int k0 = 0; k0 < K; k0 += BK) {
#pragma unroll
        for (int s = tid; s < BM * BK / 4; s += NT) {
            int arow = s / (BK / 4);
            int ac4  = s % (BK / 4);
            float4 v = make_float4(0.f, 0.f, 0.f, 0.f);
            int gr = cm + arow;
            if (gr < M)
                v = *reinterpret_cast<const float4*>(A + (size_t)gr * K + k0 + ac4 * 4);
            As[ac4 * 4 + 0][arow] = v.x;
            As[ac4 * 4 + 1][arow] = v.y;
            As[ac4 * 4 + 2][arow] = v.z;
            As[ac4 * 4 + 3][arow] = v.w;
        }
#pragma unroll
        for (int s = tid; s < BK * BN / 4; s += NT) {
            int brow = s / (BN / 4);
            int bc4  = s % (BN / 4);
            float4 v = *reinterpret_cast<const float4*>(
                B + (size_t)(k0 + brow) * Nb + cn + bc4 * 4);
            Bs[brow][bc4 * 4 + 0] = v.x;
            Bs[brow][bc4 * 4 + 1] = v.y;
            Bs[brow][bc4 * 4 + 2] = v.z;
            Bs[brow][bc4 * 4 + 3] = v.w;
        }
        __syncthreads();

#pragma unroll
        for (int kk = 0; kk < BK; kk++) {
            ull a2[TM], b2[TN / 2];
#pragma unroll
            for (int i = 0; i < TM; i++) a2[i] = dup2(As[kk][tr * TM + i]);
#pragma unroll
            for (int j = 0; j < TN / 2; j++)
                b2[j] = *reinterpret_cast<const ull*>(&Bs[kk][tc * TN + 2 * j]);
#pragma unroll
            for (int i = 0; i < TM; i++)
#pragma unroll
                for (int j = 0; j < TN / 2; j++) fma2(acc2[i][j], a2[i], b2[j]);
        }
        __syncthreads();
    }

#pragma unroll
    for (int i = 0; i < TM; i++) {
        int gr = cm + tr * TM + i;
        if (gr < M) {
            float2 p0 = unpk(acc2[i][0]);
            float2 p1 = unpk(acc2[i][1]);
            float4 v = make_float4(p0.x, p0.y, p1.x, p1.y);
            *reinterpret_cast<float4*>(C + (size_t)gr * Nb + cn + tc * TN) = v;
        }
    }
}

// ---------------- fused GGC layer: gi/gh GEMMs + GRU (+ optional s@W2) --------
template<bool DO_W2>
__global__ __launch_bounds__(256)
void ggc_fused_kernel(const float* __restrict__ u, float* __restrict__ s,
                      const float* __restrict__ Wc, const float* __restrict__ WhhT,
                      const float* __restrict__ bih, const float* __restrict__ bhh,
                      const float* __restrict__ W2, float* __restrict__ t2,
                      int n) {
    extern __shared__ __align__(16) float smem[];
    float* Wt = smem;               // [64][192]  (also reused as Snew[64][72])
    float* At = smem + 64 * 192;    // [64][72]  (k-major)

    const int tid = threadIdx.x;
    const int tr  = tid >> 4;       // node group
    const int tc  = tid & 15;       // f group
    const int nodebase = blockIdx.x * 64;

    ull ar[4][2], az[4][2], an[4][2], ah[4][2];
#pragma unroll
    for (int i = 0; i < 4; i++)
#pragma unroll
        for (int j = 0; j < 2; j++) { ar[i][j] = 0; az[i][j] = 0; an[i][j] = 0; ah[i][j] = 0; }

#pragma unroll
    for (int phase = 0; phase < 2; phase++) {
        const float* W = (phase == 0) ? Wc : WhhT;
        const float* A = (phase == 0) ? u  : s;
        for (int i = tid; i < 64 * 192 / 4; i += 256)
            *reinterpret_cast<float4*>(Wt + i * 4) =
                *reinterpret_cast<const float4*>(W + i * 4);
        {
            int nl = tid >> 2;
            int kb = (tid & 3) * 16;
            int gn = nodebase + nl;
#pragma unroll
            for (int q = 0; q < 4; q++) {
                float4 v = make_float4(0.f, 0.f, 0.f, 0.f);
                if (gn < n)
                    v = *reinterpret_cast<const float4*>(A + (size_t)gn * 64 + kb + q * 4);
                At[(kb + q * 4 + 0) * 72 + nl] = v.x;
                At[(kb + q * 4 + 1) * 72 + nl] = v.y;
                At[(kb + q * 4 + 2) * 72 + nl] = v.z;
                At[(kb + q * 4 + 3) * 72 + nl] = v.w;
            }
        }
        __syncthreads();

#pragma unroll 4
        for (int k = 0; k < 64; k++) {
            ull a2[4];
#pragma unroll
            for (int i = 0; i < 4; i++) a2[i] = dup2(At[k * 72 + tr * 4 + i]);
            const float* wr = Wt + k * 192 + tc * 4;
            ull wr2[2], wz2[2], wn2[2];
#pragma unroll
            for (int j = 0; j < 2; j++) {
                wr2[j] = *reinterpret_cast<const ull*>(wr + 2 * j);
                wz2[j] = *reinterpret_cast<const ull*>(wr + 64 + 2 * j);
                wn2[j] = *reinterpret_cast<const ull*>(wr + 128 + 2 * j);
            }
            if (phase == 0) {
#pragma unroll
                for (int i = 0; i < 4; i++)
#pragma unroll
                    for (int j = 0; j < 2; j++) {
                        fma2(ar[i][j], a2[i], wr2[j]);
                        fma2(az[i][j], a2[i], wz2[j]);
                        fma2(an[i][j], a2[i], wn2[j]);
                    }
            } else {
#pragma unroll
                for (int i = 0; i < 4; i++)
#pragma unroll
                    for (int j = 0; j < 2; j++) {
                        fma2(ar[i][j], a2[i], wr2[j]);
                        fma2(az[i][j], a2[i], wz2[j]);
                        fma2(ah[i][j], a2[i], wn2[j]);
                    }
            }
        }
        if (phase == 0) __syncthreads();
    }

    if (DO_W2) __syncthreads();   // all warps done reading Wt before Snew writes

    // epilogue: GRU. At holds the old-s tile (k-major).
    const int fb = tc * 4;
    float br[4], bz[4], bn_[4], bh_[4];
#pragma unroll
    for (int j = 0; j < 4; j++) {
        br[j]  = __ldg(bih + fb + j)       + __ldg(bhh + fb + j);
        bz[j]  = __ldg(bih + 64 + fb + j)  + __ldg(bhh + 64 + fb + j);
        bn_[j] = __ldg(bih + 128 + fb + j);
        bh_[j] = __ldg(bhh + 128 + fb + j);
    }
    float* Snew = Wt;   // [64][72], row-major per node
#pragma unroll
    for (int i = 0; i < 4; i++) {
        int nl = tr * 4 + i;
        int gn = nodebase + nl;
        float out4[4];
#pragma unroll
        for (int j2 = 0; j2 < 2; j2++) {
            float2 rv = unpk(ar[i][j2]);
            float2 zv = unpk(az[i][j2]);
            float2 nv = unpk(an[i][j2]);
            float2 hv = unpk(ah[i][j2]);
#pragma unroll
            for (int l = 0; l < 2; l++) {
                int j = j2 * 2 + l;
                float rr = sigmoidf_((l ? rv.y : rv.x) + br[j]);
                float zz = sigmoidf_((l ? zv.y : zv.x) + bz[j]);
                float in_ = (l ? nv.y : nv.x) + bn_[j];
                float hn  = (l ? hv.y : hv.x) + bh_[j];
                float ng = tanhf(in_ + rr * hn);
                float sold = At[(fb + j) * 72 + nl];
                out4[j] = (1.0f - zz) * ng + zz * sold;
            }
        }
        if (gn < n)
            *reinterpret_cast<float4*>(s + (size_t)gn * 64 + fb) =
                make_float4(out4[0], out4[1], out4[2], out4[3]);
        if (DO_W2)
            *reinterpret_cast<float4*>(Snew + nl * 72 + fb) =
                make_float4(out4[0], out4[1], out4[2], out4[3]);
    }

    if (DO_W2) {
        __syncthreads();
        // load W2 [64][16] into At region
        float* W2s = At;
        *reinterpret_cast<float4*>(W2s + tid * 4) =
            *reinterpret_cast<const float4*>(W2 + tid * 4);
        __syncthreads();
        int nl = tid >> 2;            // 0..63
        int q  = tid & 3;             // col group
        int gn = nodebase + nl;
        if (gn < n) {
            float4 acc = make_float4(0.f, 0.f, 0.f, 0.f);
#pragma unroll 8
            for (int k = 0; k < 64; k++) {
                float a = Snew[nl * 72 + k];
                float4 w4 = *reinterpret_cast<const float4*>(W2s + k * 16 + q * 4);
                acc.x = fmaf(a, w4.x, acc.x);
                acc.y = fmaf(a, w4.y, acc.y);
                acc.z = fmaf(a, w4.z, acc.z);
                acc.w = fmaf(a, w4.w, acc.w);
            }
            *reinterpret_cast<float4*>(t2 + (size_t)gn * 16 + q * 4) = acc;
        }
    }
}

// ---------------- launch -------------------------------------------------------
extern "C" void kernel_launch(void* const* d_in, const int* in_sizes, int n_in,
                              void* d_out, int out_size) {
    const float* x   = (const float*)d_in[0];
    const int*   ei  = (const int*)  d_in[1];
    const float* ew  = (const float*)d_in[2];
    const float* W1  = (const float*)d_in[3];
    const float* b1  = (const float*)d_in[4];
    const float* Wg  = (const float*)d_in[5];
    const float* Wih = (const float*)d_in[6];
    const float* Whh = (const float*)d_in[7];
    const float* bih = (const float*)d_in[8];
    const float* bhh = (const float*)d_in[9];
    const float* W2  = (const float*)d_in[10];
    const float* b2  = (const float*)d_in[11];
    float* out = (float*)d_out;

    const int n = in_sizes[0] / 512;
    const int e = in_sizes[2];
    const int* row = ei;
    const int* col = ei + e;

    float *deg, *dinv, *t1, *s, *u, *t2, *wc, *whht;
    int *off, *cur;
    ull *egcn, *eggc;
    cudaGetSymbolAddress((void**)&deg,  g_deg);
    cudaGetSymbolAddress((void**)&dinv, g_dinv);
    cudaGetSymbolAddress((void**)&t1,   g_t1);
    cudaGetSymbolAddress((void**)&s,    g_s);
    cudaGetSymbolAddress((void**)&u,    g_u);
    cudaGetSymbolAddress((void**)&t2,   g_t2);
    cudaGetSymbolAddress((void**)&off,  g_off);
    cudaGetSymbolAddress((void**)&cur,  g_cur);
    cudaGetSymbolAddress((void**)&egcn, g_egcn);
    cudaGetSymbolAddress((void**)&eggc, g_eggc);
    cudaGetSymbolAddress((void**)&wc,   g_wc);
    cudaGetSymbolAddress((void**)&whht, g_whht);

    const int TB = 256;
    const int mblocks = (n + 127) / 128;
    const int gblocks = (n + 7) / 8;
    const int fblocks = (n + 63) / 64;
    const int FUSED_SMEM = (64 * 192 + 64 * 72) * sizeof(float);   // 67584 B

    static int smem_set = 0;
    if (!smem_set) {
        cudaFuncSetAttribute(ggc_fused_kernel<false>,
                             cudaFuncAttributeMaxDynamicSharedMemorySize, FUSED_SMEM);
        cudaFuncSetAttribute(ggc_fused_kernel<true>,
                             cudaFuncAttributeMaxDynamicSharedMemorySize, FUSED_SMEM);
        smem_set = 1;
    }

    // ---- CSR build + shared gcn_norm ----
    init_kernel<<<(n + TB - 1) / TB, TB>>>(deg, cur, n);
    count_kernel<<<(e + TB - 1) / TB, TB>>>(col, ew, cur, deg, e);
    scan_dinv_kernel<<<1, 1024>>>(cur, off, cur, deg, dinv, n);
    fill_kernel<<<(e + TB - 1) / TB, TB>>>(row, col, ew, dinv, cur, egcn, eggc, e);

    // combined GGC weights
    wc_kernel<<<(64 * 192 + TB - 1) / TB, TB>>>(Wg,           Wih, wc);
    wc_kernel<<<(64 * 192 + TB - 1) / TB, TB>>>(Wg + 64 * 64, Wih, wc + 64 * 192);
    whht_kernel<<<(64 * 192 + TB - 1) / TB, TB>>>(Whh, whht);

    // ---- GCN conv 1 ----
    gemm_kernel<128, 64, 16, 8, 4><<<dim3(mblocks, 1), 256>>>(x, W1, t1, n, 512, 64);
    gather64_kernel<1><<<gblocks, 256>>>(t1, t1, s, off, egcn, dinv, b1, n);

    // ---- GatedGraphConv (2 layers, fused; layer 2 also computes t2=s@W2) ----
    gather64_kernel<0><<<gblocks, 256>>>(s, s, u, off, eggc, dinv, b1, n);
    ggc_fused_kernel<false><<<fblocks, 256, FUSED_SMEM>>>(
        u, s, wc, whht, bih, bhh, W2, t2, n);
    gather64_kernel<0><<<gblocks, 256>>>(s, s, u, off, eggc, dinv, b1, n);
    ggc_fused_kernel<true><<<fblocks, 256, FUSED_SMEM>>>(
        u, s, wc + 64 * 192, whht, bih, bhh, W2, t2, n);

    // ---- GCN conv 2 + log_softmax ----
    gather16_lsm_kernel<<<gblocks, 256>>>(t2, out, off, egcn, dinv, b2, n);
}

// round 5
// speedup vs baseline: 1.1331x; 1.1331x over previous
#include <cuda_runtime.h>
#include <cstdint>

#define MAXN 100000
#define MAXE 3200000

typedef unsigned long long ull;

// ---------------- scratch (device globals) ----------------------------------
__device__ float g_deg [MAXN];
__device__ float g_dinv[MAXN];
__device__ float g_t1  [MAXN * 64];   // x@W1
__device__ float g_s   [MAXN * 64];   // node state
__device__ float g_u   [MAXN * 64];   // gathered state (GGC)
__device__ float g_t2  [MAXN * 16];   // s@W2
// CSR
__device__ int   g_off [MAXN + 1];
__device__ int   g_cur [MAXN];
__device__ ull   g_egcn[MAXE];        // packed (src, w*dinv[src])
__device__ ull   g_eggc[MAXE];        // packed (src, w)
__device__ float g_wc  [2 * 64 * 192]; // Wg@Wih^T per layer  [k][f]
__device__ float g_whht[64 * 192];     // Whh^T               [k][f]

__device__ __forceinline__ float sigmoidf_(float x) { return 1.0f / (1.0f + expf(-x)); }

__device__ __forceinline__ ull packsw(int s, float w) {
    return ((ull)__float_as_uint(w) << 32) | (unsigned)s;
}
__device__ __forceinline__ int  pk_src(ull m) { return (int)(unsigned)m; }
__device__ __forceinline__ float pk_w(ull m)  { return __uint_as_float((unsigned)(m >> 32)); }

// ---- packed f32x2 helpers ---------------------------------------------------
__device__ __forceinline__ ull dup2(float a) {
    ull r; asm("mov.b64 %0,{%1,%1};" : "=l"(r) : "f"(a)); return r;
}
__device__ __forceinline__ void fma2(ull& d, ull a, ull b) {
    asm("fma.rn.f32x2 %0,%1,%2,%0;" : "+l"(d) : "l"(a), "l"(b));
}
__device__ __forceinline__ float2 unpk(ull v) {
    float2 f; asm("mov.b64 {%0,%1},%2;" : "=f"(f.x), "=f"(f.y) : "l"(v)); return f;
}

// ---------------- CSR build --------------------------------------------------
__global__ void init_kernel(float* deg, int* cnt, int n) {
    int i = blockIdx.x * blockDim.x + threadIdx.x;
    if (i < n) { deg[i] = 1.0f; cnt[i] = 0; }
}

__global__ void count_kernel(const int* __restrict__ col, const float* __restrict__ w,
                             int* cnt, float* deg, int e) {
    int i = blockIdx.x * blockDim.x + threadIdx.x;
    if (i < e) {
        int c = col[i];
        atomicAdd(cnt + c, 1);
        atomicAdd(deg + c, w[i]);
    }
}

__global__ void scan_kernel(const int* __restrict__ cnt, int* __restrict__ off,
                            int* __restrict__ cur, int n) {
    __shared__ int part[1024];
    int t = threadIdx.x;
    int chunk = (n + 1023) >> 10;
    int lo = t * chunk;
    int hi = min(lo + chunk, n);
    int s = 0;
    for (int i = lo; i < hi; i++) s += cnt[i];
    part[t] = s;
    __syncthreads();
    for (int d = 1; d < 1024; d <<= 1) {
        int add = (t >= d) ? part[t - d] : 0;
        __syncthreads();
        part[t] += add;
        __syncthreads();
    }
    int base = part[t] - s;   // exclusive
    for (int i = lo; i < hi; i++) {
        int c = cnt[i];       // read BEFORE cur[i] store (cnt aliases cur)
        off[i] = base; cur[i] = base;
        base += c;
    }
    if (t == 0) off[n] = part[1023];
}

__global__ void dinv_kernel(const float* __restrict__ deg, float* __restrict__ dinv, int n) {
    int i = blockIdx.x * blockDim.x + threadIdx.x;
    if (i < n) {
        float d = deg[i];
        dinv[i] = (d > 0.0f) ? rsqrtf(d) : 0.0f;
    }
}

__global__ void fill_kernel(const int* __restrict__ row, const int* __restrict__ col,
                            const float* __restrict__ w, const float* __restrict__ dinv,
                            int* cur, ull* __restrict__ egcn, ull* __restrict__ eggc, int e) {
    int i = blockIdx.x * blockDim.x + threadIdx.x;
    if (i >= e) return;
    int r = row[i];
    float ww = w[i];
    int pos = atomicAdd(cur + col[i], 1);
    eggc[pos] = packsw(r, ww);
    egcn[pos] = packsw(r, ww * __ldg(dinv + r));
}

// Wc[k,f] = sum_j Wg[layer][k][j] * Wih[f][j]   (Wc : [64,192])
__global__ void wc_kernel(const float* __restrict__ Wg, const float* __restrict__ Wih,
                          float* __restrict__ Wc) {
    int idx = blockIdx.x * blockDim.x + threadIdx.x;
    if (idx >= 64 * 192) return;
    int k = idx / 192, f = idx % 192;
    float s = 0.0f;
#pragma unroll 8
    for (int j = 0; j < 64; j++) s = fmaf(Wg[k * 64 + j], Wih[f * 64 + j], s);
    Wc[idx] = s;
}

__global__ void whht_kernel(const float* __restrict__ Whh, float* __restrict__ WhhT) {
    int idx = blockIdx.x * blockDim.x + threadIdx.x;
    if (idx >= 64 * 192) return;
    int k = idx / 192, f = idx % 192;
    WhhT[idx] = Whh[f * 64 + k];
}

// ---------------- CSR gather (F=64), fused epilogues -------------------------
// EPI 0: plain weighted sum -> dst            (GGC message aggregation)
// EPI 1: GCN1: relu(dinv*acc + dinv^2*self + bias) -> dst
template<int EPI>
__global__ __launch_bounds__(256)
void gather64_kernel(const float* __restrict__ feat, const float* __restrict__ selff,
                     float* __restrict__ dst,
                     const int* __restrict__ off, const ull* __restrict__ meta,
                     const float* __restrict__ dinv, const float* __restrict__ bias, int n) {
    int node = (blockIdx.x * blockDim.x + threadIdx.x) >> 5;
    if (node >= n) return;
    int lane = threadIdx.x & 31;
    int h = lane >> 4;        // 0/1 edge parity
    int l = lane & 15;        // float4 lane in 64-dim row

    int beg = __ldg(off + node);
    int end = __ldg(off + node + 1);

    float4 a0 = make_float4(0.f, 0.f, 0.f, 0.f);
    float4 a1 = make_float4(0.f, 0.f, 0.f, 0.f);

    int j = beg + h;
    for (; j + 2 < end; j += 4) {
        ull m0 = __ldg(meta + j);
        ull m1 = __ldg(meta + j + 2);
        float4 v0 = *reinterpret_cast<const float4*>(feat + (size_t)pk_src(m0) * 64 + l * 4);
        float4 v1 = *reinterpret_cast<const float4*>(feat + (size_t)pk_src(m1) * 64 + l * 4);
        float w0 = pk_w(m0), w1 = pk_w(m1);
        a0.x = fmaf(w0, v0.x, a0.x); a0.y = fmaf(w0, v0.y, a0.y);
        a0.z = fmaf(w0, v0.z, a0.z); a0.w = fmaf(w0, v0.w, a0.w);
        a1.x = fmaf(w1, v1.x, a1.x); a1.y = fmaf(w1, v1.y, a1.y);
        a1.z = fmaf(w1, v1.z, a1.z); a1.w = fmaf(w1, v1.w, a1.w);
    }
    for (; j < end; j += 2) {
        ull m0 = __ldg(meta + j);
        float4 v0 = *reinterpret_cast<const float4*>(feat + (size_t)pk_src(m0) * 64 + l * 4);
        float w0 = pk_w(m0);
        a0.x = fmaf(w0, v0.x, a0.x); a0.y = fmaf(w0, v0.y, a0.y);
        a0.z = fmaf(w0, v0.z, a0.z); a0.w = fmaf(w0, v0.w, a0.w);
    }
    a0.x += a1.x; a0.y += a1.y; a0.z += a1.z; a0.w += a1.w;

    a0.x += __shfl_down_sync(0xffffffffu, a0.x, 16);
    a0.y += __shfl_down_sync(0xffffffffu, a0.y, 16);
    a0.z += __shfl_down_sync(0xffffffffu, a0.z, 16);
    a0.w += __shfl_down_sync(0xffffffffu, a0.w, 16);

    if (h == 0) {
        float4 o;
        if (EPI == 1) {
            float di = __ldg(dinv + node);
            float4 sv = *reinterpret_cast<const float4*>(selff + (size_t)node * 64 + l * 4);
            float4 bv = *reinterpret_cast<const float4*>(bias + l * 4);
            o.x = fmaxf(fmaf(di, a0.x, fmaf(di * di, sv.x, bv.x)), 0.0f);
            o.y = fmaxf(fmaf(di, a0.y, fmaf(di * di, sv.y, bv.y)), 0.0f);
            o.z = fmaxf(fmaf(di, a0.z, fmaf(di * di, sv.z, bv.z)), 0.0f);
            o.w = fmaxf(fmaf(di, a0.w, fmaf(di * di, sv.w, bv.w)), 0.0f);
        } else {
            o = a0;
        }
        *reinterpret_cast<float4*>(dst + (size_t)node * 64 + l * 4) = o;
    }
}

// ---------------- CSR gather (F=16) + GCN epilogue + log_softmax --------------
__global__ __launch_bounds__(256)
void gather16_lsm_kernel(const float* __restrict__ feat, float* __restrict__ out,
                         const int* __restrict__ off, const ull* __restrict__ meta,
                         const float* __restrict__ dinv, const float* __restrict__ b2, int n) {
    int node = (blockIdx.x * blockDim.x + threadIdx.x) >> 5;
    if (node >= n) return;
    int lane = threadIdx.x & 31;
    int h = lane >> 2;        // 0..7 edge slot
    int l = lane & 3;

    int beg = __ldg(off + node);
    int end = __ldg(off + node + 1);

    float4 a = make_float4(0.f, 0.f, 0.f, 0.f);
    for (int j = beg + h; j < end; j += 8) {
        ull m = __ldg(meta + j);
        float w0 = pk_w(m);
        float4 v = *reinterpret_cast<const float4*>(feat + (size_t)pk_src(m) * 16 + l * 4);
        a.x = fmaf(w0, v.x, a.x); a.y = fmaf(w0, v.y, a.y);
        a.z = fmaf(w0, v.z, a.z); a.w = fmaf(w0, v.w, a.w);
    }
#pragma unroll
    for (int o = 16; o >= 4; o >>= 1) {
        a.x += __shfl_down_sync(0xffffffffu, a.x, o);
        a.y += __shfl_down_sync(0xffffffffu, a.y, o);
        a.z += __shfl_down_sync(0xffffffffu, a.z, o);
        a.w += __shfl_down_sync(0xffffffffu, a.w, o);
    }

    if (h == 0) {
        float di = __ldg(dinv + node);
        float4 sv = *reinterpret_cast<const float4*>(feat + (size_t)node * 16 + l * 4);
        float4 bv = *reinterpret_cast<const float4*>(b2 + l * 4);
        float4 v;
        v.x = fmaf(di, a.x, fmaf(di * di, sv.x, bv.x));
        v.y = fmaf(di, a.y, fmaf(di * di, sv.y, bv.y));
        v.z = fmaf(di, a.z, fmaf(di * di, sv.z, bv.z));
        v.w = fmaf(di, a.w, fmaf(di * di, sv.w, bv.w));
        float mx = fmaxf(fmaxf(v.x, v.y), fmaxf(v.z, v.w));
        mx = fmaxf(mx, __shfl_xor_sync(0x0000000Fu, mx, 1));
        mx = fmaxf(mx, __shfl_xor_sync(0x0000000Fu, mx, 2));
        float se = expf(v.x - mx) + expf(v.y - mx) + expf(v.z - mx) + expf(v.w - mx);
        se += __shfl_xor_sync(0x0000000Fu, se, 1);
        se += __shfl_xor_sync(0x0000000Fu, se, 2);
        float lse = mx + logf(se);
        float4 o;
        o.x = v.x - lse; o.y = v.y - lse; o.z = v.z - lse; o.w = v.w - lse;
        *reinterpret_cast<float4*>(out + (size_t)node * 16 + l * 4) = o;
    }
}

// ---------------- register-tiled fp32 GEMM with packed FFMA2 ------------------
template<int BM, int BN, int BK, int TM, int TN>
__global__ __launch_bounds__((BM/TM)*(BN/TN))
void gemm_kernel(const float* __restrict__ A, const float* __restrict__ B,
                 float* __restrict__ C, int M, int K, int Nb) {
    constexpr int NT  = (BM / TM) * (BN / TN);
    constexpr int BMP = BM + 4;
    constexpr int BNP = BN + 4;
    __shared__ __align__(16) float As[BK][BMP];
    __shared__ __align__(16) float Bs[BK][BNP];

    const int tid = threadIdx.x;
    const int tr  = tid / (BN / TN);
    const int tc  = tid % (BN / TN);
    const int cm  = blockIdx.x * BM;
    const int cn  = blockIdx.y * BN;

    ull acc2[TM][TN / 2];
#pragma unroll
    for (int i = 0; i < TM; i++)
#pragma unroll
        for (int j = 0; j < TN / 2; j++) acc2[i][j] = 0ULL;

    for (int k0 = 0; k0 < K; k0 += BK) {
#pragma unroll
        for (int s = tid; s < BM * BK / 4; s += NT) {
            int arow = s / (BK / 4);
            int ac4  = s % (BK / 4);
            float4 v = make_float4(0.f, 0.f, 0.f, 0.f);
            int gr = cm + arow;
            if (gr < M)
                v = *reinterpret_cast<const float4*>(A + (size_t)gr * K + k0 + ac4 * 4);
            As[ac4 * 4 + 0][arow] = v.x;
            As[ac4 * 4 + 1][arow] = v.y;
            As[ac4 * 4 + 2][arow] = v.z;
            As[ac4 * 4 + 3][arow] = v.w;
        }
#pragma unroll
        for (int s = tid; s < BK * BN / 4; s += NT) {
            int brow = s / (BN / 4);
            int bc4  = s % (BN / 4);
            float4 v = *reinterpret_cast<const float4*>(
                B + (size_t)(k0 + brow) * Nb + cn + bc4 * 4);
            Bs[brow][bc4 * 4 + 0] = v.x;
            Bs[brow][bc4 * 4 + 1] = v.y;
            Bs[brow][bc4 * 4 + 2] = v.z;
            Bs[brow][bc4 * 4 + 3] = v.w;
        }
        __syncthreads();

#pragma unroll
        for (int kk = 0; kk < BK; kk++) {
            ull a2[TM], b2[TN / 2];
#pragma unroll
            for (int i = 0; i < TM; i++) a2[i] = dup2(As[kk][tr * TM + i]);
#pragma unroll
            for (int j = 0; j < TN / 2; j++)
                b2[j] = *reinterpret_cast<const ull*>(&Bs[kk][tc * TN + 2 * j]);
#pragma unroll
            for (int i = 0; i < TM; i++)
#pragma unroll
                for (int j = 0; j < TN / 2; j++) fma2(acc2[i][j], a2[i], b2[j]);
        }
        __syncthreads();
    }

#pragma unroll
    for (int i = 0; i < TM; i++) {
        int gr = cm + tr * TM + i;
        if (gr < M) {
            float2 p0 = unpk(acc2[i][0]);
            float2 p1 = unpk(acc2[i][1]);
            float4 v = make_float4(p0.x, p0.y, p1.x, p1.y);
            *reinterpret_cast<float4*>(C + (size_t)gr * Nb + cn + tc * TN) = v;
        }
    }
}

// ---------------- fused GGC layer: gi/gh GEMMs + GRU (+ optional s@W2) --------
template<bool DO_W2>
__global__ __launch_bounds__(256)
void ggc_fused_kernel(const float* __restrict__ u, float* __restrict__ s,
                      const float* __restrict__ Wc, const float* __restrict__ WhhT,
                      const float* __restrict__ bih, const float* __restrict__ bhh,
                      const float* __restrict__ W2, float* __restrict__ t2,
                      int n) {
    extern __shared__ __align__(16) float smem[];
    float* Wt = smem;               // [64][192]  (reused as Snew[64][72] for W2)
    float* At = smem + 64 * 192;    // [64][72]  (k-major)

    const int tid = threadIdx.x;
    const int tr  = tid >> 4;       // node group
    const int tc  = tid & 15;       // f group
    const int nodebase = blockIdx.x * 64;

    ull ar[4][2], az[4][2], an[4][2], ah[4][2];
#pragma unroll
    for (int i = 0; i < 4; i++)
#pragma unroll
        for (int j = 0; j < 2; j++) { ar[i][j] = 0; az[i][j] = 0; an[i][j] = 0; ah[i][j] = 0; }

#pragma unroll
    for (int phase = 0; phase < 2; phase++) {
        const float* W = (phase == 0) ? Wc : WhhT;
        const float* A = (phase == 0) ? u  : s;
        for (int i = tid; i < 64 * 192 / 4; i += 256)
            *reinterpret_cast<float4*>(Wt + i * 4) =
                *reinterpret_cast<const float4*>(W + i * 4);
        {
            int nl = tid >> 2;
            int kb = (tid & 3) * 16;
            int gn = nodebase + nl;
#pragma unroll
            for (int q = 0; q < 4; q++) {
                float4 v = make_float4(0.f, 0.f, 0.f, 0.f);
                if (gn < n)
                    v = *reinterpret_cast<const float4*>(A + (size_t)gn * 64 + kb + q * 4);
                At[(kb + q * 4 + 0) * 72 + nl] = v.x;
                At[(kb + q * 4 + 1) * 72 + nl] = v.y;
                At[(kb + q * 4 + 2) * 72 + nl] = v.z;
                At[(kb + q * 4 + 3) * 72 + nl] = v.w;
            }
        }
        __syncthreads();

#pragma unroll 4
        for (int k = 0; k < 64; k++) {
            ull a2[4];
#pragma unroll
            for (int i = 0; i < 4; i++) a2[i] = dup2(At[k * 72 + tr * 4 + i]);
            const float* wr = Wt + k * 192 + tc * 4;
            ull wr2[2], wz2[2], wn2[2];
#pragma unroll
            for (int j = 0; j < 2; j++) {
                wr2[j] = *reinterpret_cast<const ull*>(wr + 2 * j);
                wz2[j] = *reinterpret_cast<const ull*>(wr + 64 + 2 * j);
                wn2[j] = *reinterpret_cast<const ull*>(wr + 128 + 2 * j);
            }
            if (phase == 0) {
#pragma unroll
                for (int i = 0; i < 4; i++)
#pragma unroll
                    for (int j = 0; j < 2; j++) {
                        fma2(ar[i][j], a2[i], wr2[j]);
                        fma2(az[i][j], a2[i], wz2[j]);
                        fma2(an[i][j], a2[i], wn2[j]);
                    }
            } else {
#pragma unroll
                for (int i = 0; i < 4; i++)
#pragma unroll
                    for (int j = 0; j < 2; j++) {
                        fma2(ar[i][j], a2[i], wr2[j]);
                        fma2(az[i][j], a2[i], wz2[j]);
                        fma2(ah[i][j], a2[i], wn2[j]);
                    }
            }
        }
        if (phase == 0) __syncthreads();
    }

    if (DO_W2) __syncthreads();   // all warps done reading Wt before Snew writes

    // epilogue: GRU. At holds the old-s tile (k-major).
    const int fb = tc * 4;
    float br[4], bz[4], bn_[4], bh_[4];
#pragma unroll
    for (int j = 0; j < 4; j++) {
        br[j]  = __ldg(bih + fb + j)       + __ldg(bhh + fb + j);
        bz[j]  = __ldg(bih + 64 + fb + j)  + __ldg(bhh + 64 + fb + j);
        bn_[j] = __ldg(bih + 128 + fb + j);
        bh_[j] = __ldg(bhh + 128 + fb + j);
    }
    float* Snew = Wt;   // [64][72]
#pragma unroll
    for (int i = 0; i < 4; i++) {
        int nl = tr * 4 + i;
        int gn = nodebase + nl;
        float out4[4];
#pragma unroll
        for (int j2 = 0; j2 < 2; j2++) {
            float2 rv = unpk(ar[i][j2]);
            float2 zv = unpk(az[i][j2]);
            float2 nv = unpk(an[i][j2]);
            float2 hv = unpk(ah[i][j2]);
#pragma unroll
            for (int l = 0; l < 2; l++) {
                int j = j2 * 2 + l;
                float rr = sigmoidf_((l ? rv.y : rv.x) + br[j]);
                float zz = sigmoidf_((l ? zv.y : zv.x) + bz[j]);
                float in_ = (l ? nv.y : nv.x) + bn_[j];
                float hn  = (l ? hv.y : hv.x) + bh_[j];
                float ng = tanhf(in_ + rr * hn);
                float sold = At[(fb + j) * 72 + nl];
                out4[j] = (1.0f - zz) * ng + zz * sold;
            }
        }
        if (gn < n)
            *reinterpret_cast<float4*>(s + (size_t)gn * 64 + fb) =
                make_float4(out4[0], out4[1], out4[2], out4[3]);
        if (DO_W2)
            *reinterpret_cast<float4*>(Snew + nl * 72 + fb) =
                make_float4(out4[0], out4[1], out4[2], out4[3]);
    }

    if (DO_W2) {
        __syncthreads();
        float* W2s = At;              // load W2 [64][16] into At region
        *reinterpret_cast<float4*>(W2s + tid * 4) =
            *reinterpret_cast<const float4*>(W2 + tid * 4);
        __syncthreads();
        int nl = tid >> 2;            // 0..63
        int q  = tid & 3;             // col group
        int gn = nodebase + nl;
        if (gn < n) {
            float4 acc = make_float4(0.f, 0.f, 0.f, 0.f);
#pragma unroll 8
            for (int k = 0; k < 64; k++) {
                float a = Snew[nl * 72 + k];
                float4 w4 = *reinterpret_cast<const float4*>(W2s + k * 16 + q * 4);
                acc.x = fmaf(a, w4.x, acc.x);
                acc.y = fmaf(a, w4.y, acc.y);
                acc.z = fmaf(a, w4.z, acc.z);
                acc.w = fmaf(a, w4.w, acc.w);
            }
            *reinterpret_cast<float4*>(t2 + (size_t)gn * 16 + q * 4) = acc;
        }
    }
}

// ---------------- launch -------------------------------------------------------
extern "C" void kernel_launch(void* const* d_in, const int* in_sizes, int n_in,
                              void* d_out, int out_size) {
    const float* x   = (const float*)d_in[0];
    const int*   ei  = (const int*)  d_in[1];
    const float* ew  = (const float*)d_in[2];
    const float* W1  = (const float*)d_in[3];
    const float* b1  = (const float*)d_in[4];
    const float* Wg  = (const float*)d_in[5];
    const float* Wih = (const float*)d_in[6];
    const float* Whh = (const float*)d_in[7];
    const float* bih = (const float*)d_in[8];
    const float* bhh = (const float*)d_in[9];
    const float* W2  = (const float*)d_in[10];
    const float* b2  = (const float*)d_in[11];
    float* out = (float*)d_out;

    const int n = in_sizes[0] / 512;
    const int e = in_sizes[2];
    const int* row = ei;
    const int* col = ei + e;

    float *deg, *dinv, *t1, *s, *u, *t2, *wc, *whht;
    int *off, *cur;
    ull *egcn, *eggc;
    cudaGetSymbolAddress((void**)&deg,  g_deg);
    cudaGetSymbolAddress((void**)&dinv, g_dinv);
    cudaGetSymbolAddress((void**)&t1,   g_t1);
    cudaGetSymbolAddress((void**)&s,    g_s);
    cudaGetSymbolAddress((void**)&u,    g_u);
    cudaGetSymbolAddress((void**)&t2,   g_t2);
    cudaGetSymbolAddress((void**)&off,  g_off);
    cudaGetSymbolAddress((void**)&cur,  g_cur);
    cudaGetSymbolAddress((void**)&egcn, g_egcn);
    cudaGetSymbolAddress((void**)&eggc, g_eggc);
    cudaGetSymbolAddress((void**)&wc,   g_wc);
    cudaGetSymbolAddress((void**)&whht, g_whht);

    const int TB = 256;
    const int mblocks = (n + 127) / 128;
    const int gblocks = (n + 7) / 8;
    const int fblocks = (n + 63) / 64;
    const int FUSED_SMEM = (64 * 192 + 64 * 72) * sizeof(float);   // 67584 B

    cudaFuncSetAttribute(ggc_fused_kernel<false>,
                         cudaFuncAttributeMaxDynamicSharedMemorySize, FUSED_SMEM);
    cudaFuncSetAttribute(ggc_fused_kernel<true>,
                         cudaFuncAttributeMaxDynamicSharedMemorySize, FUSED_SMEM);

    // ---- CSR build + shared gcn_norm ----
    init_kernel<<<(n + TB - 1) / TB, TB>>>(deg, cur, n);
    count_kernel<<<(e + TB - 1) / TB, TB>>>(col, ew, cur, deg, e);
    scan_kernel<<<1, 1024>>>(cur, off, cur, n);
    dinv_kernel<<<(n + TB - 1) / TB, TB>>>(deg, dinv, n);
    fill_kernel<<<(e + TB - 1) / TB, TB>>>(row, col, ew, dinv, cur, egcn, eggc, e);

    // combined GGC weights
    wc_kernel<<<(64 * 192 + TB - 1) / TB, TB>>>(Wg,           Wih, wc);
    wc_kernel<<<(64 * 192 + TB - 1) / TB, TB>>>(Wg + 64 * 64, Wih, wc + 64 * 192);
    whht_kernel<<<(64 * 192 + TB - 1) / TB, TB>>>(Whh, whht);

    // ---- GCN conv 1 ----
    gemm_kernel<128, 64, 16, 8, 4><<<dim3(mblocks, 1), 256>>>(x, W1, t1, n, 512, 64);
    gather64_kernel<1><<<gblocks, 256>>>(t1, t1, s, off, egcn, dinv, b1, n);

    // ---- GatedGraphConv (2 layers, fused; layer 2 also computes t2=s@W2) ----
    gather64_kernel<0><<<gblocks, 256>>>(s, s, u, off, eggc, dinv, b1, n);
    ggc_fused_kernel<false><<<fblocks, 256, FUSED_SMEM>>>(
        u, s, wc, whht, bih, bhh, W2, t2, n);
    gather64_kernel<0><<<gblocks, 256>>>(s, s, u, off, eggc, dinv, b1, n);
    ggc_fused_kernel<true><<<fblocks, 256, FUSED_SMEM>>>(
        u, s, wc + 64 * 192, whht, bih, bhh, W2, t2, n);

    // ---- GCN conv 2 + log_softmax ----
    gather16_lsm_kernel<<<gblocks, 256>>>(t2, out, off, egcn, dinv, b2, n);
}

// round 7
// speedup vs baseline: 1.2007x; 1.0596x over previous
#include <cuda_runtime.h>
#include <cstdint>

#define MAXN 100000
#define MAXE 3200000

typedef unsigned long long ull;

// ---------------- scratch (device globals) ----------------------------------
__device__ float g_deg [MAXN];
__device__ float g_dinv[MAXN];
__device__ float g_t1  [MAXN * 64];   // x@W1
__device__ float g_s   [MAXN * 64];   // node state
__device__ float g_u   [MAXN * 64];   // gathered state (GGC)
__device__ float g_t2  [MAXN * 16];   // s@W2
// CSR
__device__ int   g_off [MAXN + 1];
__device__ int   g_cur [MAXN];
__device__ ull   g_egcn[MAXE];        // packed (src, w*dinv[src])
__device__ ull   g_eggc[MAXE];        // packed (src, w)
__device__ float g_wc  [2 * 64 * 192]; // Wg@Wih^T per layer  [k][f]
__device__ float g_whht[64 * 192];     // Whh^T               [k][f]

__device__ __forceinline__ float sigmoidf_(float x) { return 1.0f / (1.0f + expf(-x)); }

__device__ __forceinline__ ull packsw(int s, float w) {
    return ((ull)__float_as_uint(w) << 32) | (unsigned)s;
}
__device__ __forceinline__ int  pk_src(ull m) { return (int)(unsigned)m; }
__device__ __forceinline__ float pk_w(ull m)  { return __uint_as_float((unsigned)(m >> 32)); }

// ---- packed f32x2 helpers ---------------------------------------------------
__device__ __forceinline__ ull dup2(float a) {
    ull r; asm("mov.b64 %0,{%1,%1};" : "=l"(r) : "f"(a)); return r;
}
__device__ __forceinline__ void fma2(ull& d, ull a, ull b) {
    asm("fma.rn.f32x2 %0,%1,%2,%0;" : "+l"(d) : "l"(a), "l"(b));
}
__device__ __forceinline__ float2 unpk(ull v) {
    float2 f; asm("mov.b64 {%0,%1},%2;" : "=f"(f.x), "=f"(f.y) : "l"(v)); return f;
}

// ---------------- CSR build --------------------------------------------------
__global__ void init_kernel(float* deg, int* cnt, int n) {
    int i = blockIdx.x * blockDim.x + threadIdx.x;
    if (i < n) { deg[i] = 1.0f; cnt[i] = 0; }
}

__global__ void count_kernel(const int* __restrict__ col, const float* __restrict__ w,
                             int* cnt, float* deg, int e) {
    int i = blockIdx.x * blockDim.x + threadIdx.x;
    if (i < e) {
        int c = col[i];
        atomicAdd(cnt + c, 1);
        atomicAdd(deg + c, w[i]);
    }
}

__global__ void scan_kernel(const int* __restrict__ cnt, int* __restrict__ off,
                            int* __restrict__ cur, int n) {
    __shared__ int part[1024];
    int t = threadIdx.x;
    int chunk = (n + 1023) >> 10;
    int lo = t * chunk;
    int hi = min(lo + chunk, n);
    int s = 0;
    for (int i = lo; i < hi; i++) s += cnt[i];
    part[t] = s;
    __syncthreads();
    for (int d = 1; d < 1024; d <<= 1) {
        int add = (t >= d) ? part[t - d] : 0;
        __syncthreads();
        part[t] += add;
        __syncthreads();
    }
    int base = part[t] - s;   // exclusive
    for (int i = lo; i < hi; i++) {
        int c = cnt[i];       // read BEFORE cur[i] store (cnt aliases cur)
        off[i] = base; cur[i] = base;
        base += c;
    }
    if (t == 0) off[n] = part[1023];
}

__global__ void dinv_kernel(const float* __restrict__ deg, float* __restrict__ dinv, int n) {
    int i = blockIdx.x * blockDim.x + threadIdx.x;
    if (i < n) {
        float d = deg[i];
        dinv[i] = (d > 0.0f) ? rsqrtf(d) : 0.0f;
    }
}

__global__ void fill_kernel(const int* __restrict__ row, const int* __restrict__ col,
                            const float* __restrict__ w, const float* __restrict__ dinv,
                            int* cur, ull* __restrict__ egcn, ull* __restrict__ eggc, int e) {
    int i = blockIdx.x * blockDim.x + threadIdx.x;
    if (i >= e) return;
    int r = row[i];
    float ww = w[i];
    int pos = atomicAdd(cur + col[i], 1);
    eggc[pos] = packsw(r, ww);
    egcn[pos] = packsw(r, ww * __ldg(dinv + r));
}

// Wc[k,f] = sum_j Wg[layer][k][j] * Wih[f][j]   (Wc : [64,192])
__global__ void wc_kernel(const float* __restrict__ Wg, const float* __restrict__ Wih,
                          float* __restrict__ Wc) {
    int idx = blockIdx.x * blockDim.x + threadIdx.x;
    if (idx >= 64 * 192) return;
    int k = idx / 192, f = idx % 192;
    float s = 0.0f;
#pragma unroll 8
    for (int j = 0; j < 64; j++) s = fmaf(Wg[k * 64 + j], Wih[f * 64 + j], s);
    Wc[idx] = s;
}

__global__ void whht_kernel(const float* __restrict__ Whh, float* __restrict__ WhhT) {
    int idx = blockIdx.x * blockDim.x + threadIdx.x;
    if (idx >= 64 * 192) return;
    int k = idx / 192, f = idx % 192;
    WhhT[idx] = Whh[f * 64 + k];
}

// ---------------- CSR gather (F=64), fused epilogues -------------------------
template<int EPI>
__global__ __launch_bounds__(256)
void gather64_kernel(const float* __restrict__ feat, const float* __restrict__ selff,
                     float* __restrict__ dst,
                     const int* __restrict__ off, const ull* __restrict__ meta,
                     const float* __restrict__ dinv, const float* __restrict__ bias, int n) {
    int node = (blockIdx.x * blockDim.x + threadIdx.x) >> 5;
    if (node >= n) return;
    int lane = threadIdx.x & 31;
    int h = lane >> 4;        // 0/1 edge parity
    int l = lane & 15;        // float4 lane in 64-dim row

    int beg = __ldg(off + node);
    int end = __ldg(off + node + 1);

    float4 a0 = make_float4(0.f, 0.f, 0.f, 0.f);
    float4 a1 = make_float4(0.f, 0.f, 0.f, 0.f);

    int j = beg + h;
    for (; j + 2 < end; j += 4) {
        ull m0 = __ldg(meta + j);
        ull m1 = __ldg(meta + j + 2);
        float4 v0 = *reinterpret_cast<const float4*>(feat + (size_t)pk_src(m0) * 64 + l * 4);
        float4 v1 = *reinterpret_cast<const float4*>(feat + (size_t)pk_src(m1) * 64 + l * 4);
        float w0 = pk_w(m0), w1 = pk_w(m1);
        a0.x = fmaf(w0, v0.x, a0.x); a0.y = fmaf(w0, v0.y, a0.y);
        a0.z = fmaf(w0, v0.z, a0.z); a0.w = fmaf(w0, v0.w, a0.w);
        a1.x = fmaf(w1, v1.x, a1.x); a1.y = fmaf(w1, v1.y, a1.y);
        a1.z = fmaf(w1, v1.z, a1.z); a1.w = fmaf(w1, v1.w, a1.w);
    }
    for (; j < end; j += 2) {
        ull m0 = __ldg(meta + j);
        float4 v0 = *reinterpret_cast<const float4*>(feat + (size_t)pk_src(m0) * 64 + l * 4);
        float w0 = pk_w(m0);
        a0.x = fmaf(w0, v0.x, a0.x); a0.y = fmaf(w0, v0.y, a0.y);
        a0.z = fmaf(w0, v0.z, a0.z); a0.w = fmaf(w0, v0.w, a0.w);
    }
    a0.x += a1.x; a0.y += a1.y; a0.z += a1.z; a0.w += a1.w;

    a0.x += __shfl_down_sync(0xffffffffu, a0.x, 16);
    a0.y += __shfl_down_sync(0xffffffffu, a0.y, 16);
    a0.z += __shfl_down_sync(0xffffffffu, a0.z, 16);
    a0.w += __shfl_down_sync(0xffffffffu, a0.w, 16);

    if (h == 0) {
        float4 o;
        if (EPI == 1) {
            float di = __ldg(dinv + node);
            float4 sv = *reinterpret_cast<const float4*>(selff + (size_t)node * 64 + l * 4);
            float4 bv = *reinterpret_cast<const float4*>(bias + l * 4);
            o.x = fmaxf(fmaf(di, a0.x, fmaf(di * di, sv.x, bv.x)), 0.0f);
            o.y = fmaxf(fmaf(di, a0.y, fmaf(di * di, sv.y, bv.y)), 0.0f);
            o.z = fmaxf(fmaf(di, a0.z, fmaf(di * di, sv.z, bv.z)), 0.0f);
            o.w = fmaxf(fmaf(di, a0.w, fmaf(di * di, sv.w, bv.w)), 0.0f);
        } else {
            o = a0;
        }
        *reinterpret_cast<float4*>(dst + (size_t)node * 64 + l * 4) = o;
    }
}

// ---------------- CSR gather (F=16) + GCN epilogue + log_softmax --------------
__global__ __launch_bounds__(256)
void gather16_lsm_kernel(const float* __restrict__ feat, float* __restrict__ out,
                         const int* __restrict__ off, const ull* __restrict__ meta,
                         const float* __restrict__ dinv, const float* __restrict__ b2, int n) {
    int node = (blockIdx.x * blockDim.x + threadIdx.x) >> 5;
    if (node >= n) return;
    int lane = threadIdx.x & 31;
    int h = lane >> 2;        // 0..7 edge slot
    int l = lane & 3;

    int beg = __ldg(off + node);
    int end = __ldg(off + node + 1);

    float4 a = make_float4(0.f, 0.f, 0.f, 0.f);
    for (int j = beg + h; j < end; j += 8) {
        ull m = __ldg(meta + j);
        float w0 = pk_w(m);
        float4 v = *reinterpret_cast<const float4*>(feat + (size_t)pk_src(m) * 16 + l * 4);
        a.x = fmaf(w0, v.x, a.x); a.y = fmaf(w0, v.y, a.y);
        a.z = fmaf(w0, v.z, a.z); a.w = fmaf(w0, v.w, a.w);
    }
#pragma unroll
    for (int o = 16; o >= 4; o >>= 1) {
        a.x += __shfl_down_sync(0xffffffffu, a.x, o);
        a.y += __shfl_down_sync(0xffffffffu, a.y, o);
        a.z += __shfl_down_sync(0xffffffffu, a.z, o);
        a.w += __shfl_down_sync(0xffffffffu, a.w, o);
    }

    if (h == 0) {
        float di = __ldg(dinv + node);
        float4 sv = *reinterpret_cast<const float4*>(feat + (size_t)node * 16 + l * 4);
        float4 bv = *reinterpret_cast<const float4*>(b2 + l * 4);
        float4 v;
        v.x = fmaf(di, a.x, fmaf(di * di, sv.x, bv.x));
        v.y = fmaf(di, a.y, fmaf(di * di, sv.y, bv.y));
        v.z = fmaf(di, a.z, fmaf(di * di, sv.z, bv.z));
        v.w = fmaf(di, a.w, fmaf(di * di, sv.w, bv.w));
        float mx = fmaxf(fmaxf(v.x, v.y), fmaxf(v.z, v.w));
        mx = fmaxf(mx, __shfl_xor_sync(0x0000000Fu, mx, 1));
        mx = fmaxf(mx, __shfl_xor_sync(0x0000000Fu, mx, 2));
        float se = expf(v.x - mx) + expf(v.y - mx) + expf(v.z - mx) + expf(v.w - mx);
        se += __shfl_xor_sync(0x0000000Fu, se, 1);
        se += __shfl_xor_sync(0x0000000Fu, se, 2);
        float lse = mx + logf(se);
        float4 o;
        o.x = v.x - lse; o.y = v.y - lse; o.z = v.z - lse; o.w = v.w - lse;
        *reinterpret_cast<float4*>(out + (size_t)node * 16 + l * 4) = o;
    }
}

// ---------------- register-tiled fp32 GEMM with packed FFMA2 ------------------
template<int BM, int BN, int BK, int TM, int TN>
__global__ __launch_bounds__((BM/TM)*(BN/TN))
void gemm_kernel(const float* __restrict__ A, const float* __restrict__ B,
                 float* __restrict__ C, int M, int K, int Nb) {
    constexpr int NT  = (BM / TM) * (BN / TN);
    constexpr int BMP = BM + 4;
    constexpr int BNP = BN + 4;
    __shared__ __align__(16) float As[BK][BMP];
    __shared__ __align__(16) float Bs[BK][BNP];

    const int tid = threadIdx.x;
    const int tr  = tid / (BN / TN);
    const int tc  = tid % (BN / TN);
    const int cm  = blockIdx.x * BM;
    const int cn  = blockIdx.y * BN;

    ull acc2[TM][TN / 2];
#pragma unroll
    for (int i = 0; i < TM; i++)
#pragma unroll
        for (int j = 0; j < TN / 2; j++) acc2[i][j] = 0ULL;

    for (int k0 = 0; k0 < K; k0 += BK) {
#pragma unroll
        for (int s = tid; s < BM * BK / 4; s += NT) {
            int arow = s / (BK / 4);
            int ac4  = s % (BK / 4);
            float4 v = make_float4(0.f, 0.f, 0.f, 0.f);
            int gr = cm + arow;
            if (gr < M)
                v = *reinterpret_cast<const float4*>(A + (size_t)gr * K + k0 + ac4 * 4);
            As[ac4 * 4 + 0][arow] = v.x;
            As[ac4 * 4 + 1][arow] = v.y;
            As[ac4 * 4 + 2][arow] = v.z;
            As[ac4 * 4 + 3][arow] = v.w;
        }
#pragma unroll
        for (int s = tid; s < BK * BN / 4; s += NT) {
            int brow = s / (BN / 4);
            int bc4  = s % (BN / 4);
            float4 v = *reinterpret_cast<const float4*>(
                B + (size_t)(k0 + brow) * Nb + cn + bc4 * 4);
            Bs[brow][bc4 * 4 + 0] = v.x;
            Bs[brow][bc4 * 4 + 1] = v.y;
            Bs[brow][bc4 * 4 + 2] = v.z;
            Bs[brow][bc4 * 4 + 3] = v.w;
        }
        __syncthreads();

#pragma unroll
        for (int kk = 0; kk < BK; kk++) {
            ull a2[TM], b2[TN / 2];
#pragma unroll
            for (int i = 0; i < TM; i++) a2[i] = dup2(As[kk][tr * TM + i]);
#pragma unroll
            for (int j = 0; j < TN / 2; j++)
                b2[j] = *reinterpret_cast<const ull*>(&Bs[kk][tc * TN + 2 * j]);
#pragma unroll
            for (int i = 0; i < TM; i++)
#pragma unroll
                for (int j = 0; j < TN / 2; j++) fma2(acc2[i][j], a2[i], b2[j]);
        }
        __syncthreads();
    }

#pragma unroll
    for (int i = 0; i < TM; i++) {
        int gr = cm + tr * TM + i;
        if (gr < M) {
            float2 p0 = unpk(acc2[i][0]);
            float2 p1 = unpk(acc2[i][1]);
            float4 v = make_float4(p0.x, p0.y, p1.x, p1.y);
            *reinterpret_cast<float4*>(C + (size_t)gr * Nb + cn + tc * TN) = v;
        }
    }
}

// ---------------- fused GGC layer: gi/gh GEMMs + GRU (+ optional s@W2) --------
template<bool DO_W2>
__global__ __launch_bounds__(256)
void ggc_fused_kernel(const float* __restrict__ u, float* __restrict__ s,
                      const float* __restrict__ Wc, const float* __restrict__ WhhT,
                      const float* __restrict__ bih, const float* __restrict__ bhh,
                      const float* __restrict__ W2, float* __restrict__ t2,
                      int n) {
    extern __shared__ __align__(16) float smem[];
    float* Wt = smem;               // [64][192]  (reused as Snew[64][72] for W2)
    float* At = smem + 64 * 192;    // [64][72]  (k-major)

    const int tid = threadIdx.x;
    const int tr  = tid >> 4;       // node group
    const int tc  = tid & 15;       // f group
    const int nodebase = blockIdx.x * 64;

    ull ar[4][2], az[4][2], an[4][2], ah[4][2];
#pragma unroll
    for (int i = 0; i < 4; i++)
#pragma unroll
        for (int j = 0; j < 2; j++) { ar[i][j] = 0; az[i][j] = 0; an[i][j] = 0; ah[i][j] = 0; }

#pragma unroll
    for (int phase = 0; phase < 2; phase++) {
        const float* W = (phase == 0) ? Wc : WhhT;
        const float* A = (phase == 0) ? u  : s;
        for (int i = tid; i < 64 * 192 / 4; i += 256)
            *reinterpret_cast<float4*>(Wt + i * 4) =
                *reinterpret_cast<const float4*>(W + i * 4);
        {
            int nl = tid >> 2;
            int kb = (tid & 3) * 16;
            int gn = nodebase + nl;
#pragma unroll
            for (int q = 0; q < 4; q++) {
                float4 v = make_float4(0.f, 0.f, 0.f, 0.f);
                if (gn < n)
                    v = *reinterpret_cast<const float4*>(A + (size_t)gn * 64 + kb + q * 4);
                At[(kb + q * 4 + 0) * 72 + nl] = v.x;
                At[(kb + q * 4 + 1) * 72 + nl] = v.y;
                At[(kb + q * 4 + 2) * 72 + nl] = v.z;
                At[(kb + q * 4 + 3) * 72 + nl] = v.w;
            }
        }
        __syncthreads();

#pragma unroll 4
        for (int k = 0; k < 64; k++) {
            ull a2[4];
#pragma unroll
            for (int i = 0; i < 4; i++) a2[i] = dup2(At[k * 72 + tr * 4 + i]);
            const float* wr = Wt + k * 192 + tc * 4;
            ull wr2[2], wz2[2], wn2[2];
#pragma unroll
            for (int j = 0; j < 2; j++) {
                wr2[j] = *reinterpret_cast<const ull*>(wr + 2 * j);
                wz2[j] = *reinterpret_cast<const ull*>(wr + 64 + 2 * j);
                wn2[j] = *reinterpret_cast<const ull*>(wr + 128 + 2 * j);
            }
            if (phase == 0) {
#pragma unroll
                for (int i = 0; i < 4; i++)
#pragma unroll
                    for (int j = 0; j < 2; j++) {
                        fma2(ar[i][j], a2[i], wr2[j]);
                        fma2(az[i][j], a2[i], wz2[j]);
                        fma2(an[i][j], a2[i], wn2[j]);
                    }
            } else {
#pragma unroll
                for (int i = 0; i < 4; i++)
#pragma unroll
                    for (int j = 0; j < 2; j++) {
                        fma2(ar[i][j], a2[i], wr2[j]);
                        fma2(az[i][j], a2[i], wz2[j]);
                        fma2(ah[i][j], a2[i], wn2[j]);
                    }
            }
        }
        if (phase == 0) __syncthreads();
    }

    if (DO_W2) __syncthreads();   // all warps done reading Wt before Snew writes

    // epilogue: GRU. At holds the old-s tile (k-major).
    const int fb = tc * 4;
    float br[4], bz[4], bn_[4], bh_[4];
#pragma unroll
    for (int j = 0; j < 4; j++) {
        br[j]  = __ldg(bih + fb + j)       + __ldg(bhh + fb + j);
        bz[j]  = __ldg(bih + 64 + fb + j)  + __ldg(bhh + 64 + fb + j);
        bn_[j] = __ldg(bih + 128 + fb + j);
        bh_[j] = __ldg(bhh + 128 + fb + j);
    }
    float* Snew = Wt;   // [64][72]
#pragma unroll
    for (int i = 0; i < 4; i++) {
        int nl = tr * 4 + i;
        int gn = nodebase + nl;
        float out4[4];
#pragma unroll
        for (int j2 = 0; j2 < 2; j2++) {
            float2 rv = unpk(ar[i][j2]);
            float2 zv = unpk(az[i][j2]);
            float2 nv = unpk(an[i][j2]);
            float2 hv = unpk(ah[i][j2]);
#pragma unroll
            for (int l = 0; l < 2; l++) {
                int j = j2 * 2 + l;
                float rr = sigmoidf_((l ? rv.y : rv.x) + br[j]);
                float zz = sigmoidf_((l ? zv.y : zv.x) + bz[j]);
                float in_ = (l ? nv.y : nv.x) + bn_[j];
                float hn  = (l ? hv.y : hv.x) + bh_[j];
                float ng = tanhf(in_ + rr * hn);
                float sold = At[(fb + j) * 72 + nl];
                out4[j] = (1.0f - zz) * ng + zz * sold;
            }
        }
        if (gn < n)
            *reinterpret_cast<float4*>(s + (size_t)gn * 64 + fb) =
                make_float4(out4[0], out4[1], out4[2], out4[3]);
        if (DO_W2)
            *reinterpret_cast<float4*>(Snew + nl * 72 + fb) =
                make_float4(out4[0], out4[1], out4[2], out4[3]);
    }

    if (DO_W2) {
        __syncthreads();
        float* W2s = At;              // load W2 [64][16] into At region
        *reinterpret_cast<float4*>(W2s + tid * 4) =
            *reinterpret_cast<const float4*>(W2 + tid * 4);
        __syncthreads();
        int nl = tid >> 2;            // 0..63
        int q  = tid & 3;             // col group
        int gn = nodebase + nl;
        if (gn < n) {
            float4 acc = make_float4(0.f, 0.f, 0.f, 0.f);
#pragma unroll 8
            for (int k = 0; k < 64; k++) {
                float a = Snew[nl * 72 + k];
                float4 w4 = *reinterpret_cast<const float4*>(W2s + k * 16 + q * 4);
                acc.x = fmaf(a, w4.x, acc.x);
                acc.y = fmaf(a, w4.y, acc.y);
                acc.z = fmaf(a, w4.z, acc.z);
                acc.w = fmaf(a, w4.w, acc.w);
            }
            *reinterpret_cast<float4*>(t2 + (size_t)gn * 16 + q * 4) = acc;
        }
    }
}

// ---------------- launch -------------------------------------------------------
extern "C" void kernel_launch(void* const* d_in, const int* in_sizes, int n_in,
                              void* d_out, int out_size) {
    const float* x   = (const float*)d_in[0];
    const int*   ei  = (const int*)  d_in[1];
    const float* ew  = (const float*)d_in[2];
    const float* W1  = (const float*)d_in[3];
    const float* b1  = (const float*)d_in[4];
    const float* Wg  = (const float*)d_in[5];
    const float* Wih = (const float*)d_in[6];
    const float* Whh = (const float*)d_in[7];
    const float* bih = (const float*)d_in[8];
    const float* bhh = (const float*)d_in[9];
    const float* W2  = (const float*)d_in[10];
    const float* b2  = (const float*)d_in[11];
    float* out = (float*)d_out;

    const int n = in_sizes[0] / 512;
    const int e = in_sizes[2];
    const int* row = ei;
    const int* col = ei + e;

    float *deg, *dinv, *t1, *s, *u, *t2, *wc, *whht;
    int *off, *cur;
    ull *egcn, *eggc;
    cudaGetSymbolAddress((void**)&deg,  g_deg);
    cudaGetSymbolAddress((void**)&dinv, g_dinv);
    cudaGetSymbolAddress((void**)&t1,   g_t1);
    cudaGetSymbolAddress((void**)&s,    g_s);
    cudaGetSymbolAddress((void**)&u,    g_u);
    cudaGetSymbolAddress((void**)&t2,   g_t2);
    cudaGetSymbolAddress((void**)&off,  g_off);
    cudaGetSymbolAddress((void**)&cur,  g_cur);
    cudaGetSymbolAddress((void**)&egcn, g_egcn);
    cudaGetSymbolAddress((void**)&eggc, g_eggc);
    cudaGetSymbolAddress((void**)&wc,   g_wc);
    cudaGetSymbolAddress((void**)&whht, g_whht);

    const int TB = 256;
    const int mblocks = (n + 127) / 128;
    const int gblocks = (n + 7) / 8;
    const int fblocks = (n + 63) / 64;
    const int FUSED_SMEM = (64 * 192 + 64 * 72) * sizeof(float);   // 67584 B

    cudaFuncSetAttribute(ggc_fused_kernel<false>,
                         cudaFuncAttributeMaxDynamicSharedMemorySize, FUSED_SMEM);
    cudaFuncSetAttribute(ggc_fused_kernel<true>,
                         cudaFuncAttributeMaxDynamicSharedMemorySize, FUSED_SMEM);

    // ---- fork a second stream for the dense-prep chain (GEMM + wc/whht) ----
    cudaStream_t s2 = 0;
    cudaEvent_t ev_fork = 0, ev_join = 0;
    bool forked = (cudaStreamCreateWithFlags(&s2, cudaStreamNonBlocking) == cudaSuccess) &&
                  (cudaEventCreateWithFlags(&ev_fork, cudaEventDisableTiming) == cudaSuccess) &&
                  (cudaEventCreateWithFlags(&ev_join, cudaEventDisableTiming) == cudaSuccess);
    cudaStream_t sb = forked ? s2 : (cudaStream_t)0;   // dense-prep stream

    if (forked) {
        cudaEventRecord(ev_fork, 0);            // fork point on capture stream
        cudaStreamWaitEvent(s2, ev_fork, 0);
    }

    // ---- Chain B (stream sb): x@W1 GEMM + combined GGC weights ----
    gemm_kernel<128, 64, 16, 8, 4><<<dim3(mblocks, 1), 256, 0, sb>>>(x, W1, t1, n, 512, 64);
    wc_kernel<<<(64 * 192 + TB - 1) / TB, TB, 0, sb>>>(Wg,           Wih, wc);
    wc_kernel<<<(64 * 192 + TB - 1) / TB, TB, 0, sb>>>(Wg + 64 * 64, Wih, wc + 64 * 192);
    whht_kernel<<<(64 * 192 + TB - 1) / TB, TB, 0, sb>>>(Whh, whht);

    // ---- Chain A (default stream): CSR build + shared gcn_norm ----
    init_kernel<<<(n + TB - 1) / TB, TB>>>(deg, cur, n);
    count_kernel<<<(e + TB - 1) / TB, TB>>>(col, ew, cur, deg, e);
    scan_kernel<<<1, 1024>>>(cur, off, cur, n);
    dinv_kernel<<<(n + TB - 1) / TB, TB>>>(deg, dinv, n);
    fill_kernel<<<(e + TB - 1) / TB, TB>>>(row, col, ew, dinv, cur, egcn, eggc, e);

    if (forked) {                                // join before first consumer
        cudaEventRecord(ev_join, s2);
        cudaStreamWaitEvent(0, ev_join, 0);
    }

    // ---- GCN conv 1 ----
    gather64_kernel<1><<<gblocks, 256>>>(t1, t1, s, off, egcn, dinv, b1, n);

    // ---- GatedGraphConv (2 layers, fused; layer 2 also computes t2=s@W2) ----
    gather64_kernel<0><<<gblocks, 256>>>(s, s, u, off, eggc, dinv, b1, n);
    ggc_fused_kernel<false><<<fblocks, 256, FUSED_SMEM>>>(
        u, s, wc, whht, bih, bhh, W2, t2, n);
    gather64_kernel<0><<<gblocks, 256>>>(s, s, u, off, eggc, dinv, b1, n);
    ggc_fused_kernel<true><<<fblocks, 256, FUSED_SMEM>>>(
        u, s, wc + 64 * 192, whht, bih, bhh, W2, t2, n);

    // ---- GCN conv 2 + log_softmax ----
    gather16_lsm_kernel<<<gblocks, 256>>>(t2, out, off, egcn, dinv, b2, n);

    // NOTE: s2 / events deliberately not destroyed here — destroying a forked
    // stream before EndCapture would invalidate the capture. kernel_launch is
    // invoked only a handful of times (correctness + capture), so the handle
    // leak is bounded and allocates no tracked device memory.
}